// round 14
// baseline (speedup 1.0000x reference)
#include <cuda_runtime.h>
#include <math.h>

#define Bn 64
#define Cn 3
#define Hn 512
#define Wn 512
#define HW (Hn * Wn)
#define CHW (Cn * HW)
#define CUT_H 256
#define CUT_W 256

#define TW 32              // tile width (x)
#define TH 16              // tile height (y)
#define NTILES 512         // (512/32)*(512/16) tiles per batch
#define SBH 47             // max staged rows (worst 46)
#define SBW 52             // smem row stride in floats (worst tap 48 -> +1 = 49)
#define SCH (SBH * SBW)    // floats per channel (2444)

struct __align__(16) BatchParams {
    float Ax, Bx, Cx, Ay, By, Cy;   // fx = Ax*x + Bx*y + Cx (flip folded in)
    float bb, cc, ss;
    int   cut, y0, x0;
    int   vec, pad0, pad1, pad2;
};

__device__ BatchParams g_params[Bn];
__device__ int4 g_tile[Bn * NTILES];   // {xa, ys0, rows|cols4<<8|interior<<16, 0}

__device__ __forceinline__ float reflect_coord(float v, float size) {
    v = fabsf(v + 0.5f);
    v = fmodf(v, 2.0f * size);
    v = fminf(v, 2.0f * size - v);
    return fminf(fmaxf(v - 0.5f, 0.0f), size - 1.0f);
}

__device__ __forceinline__ void reflect_range(float a, float b,
                                              float& lo, float& hi) {
    const float ra = reflect_coord(a, 512.0f);
    const float rb = reflect_coord(b, 512.0f);
    lo = fminf(ra, rb);
    hi = fmaxf(ra, rb);
    if (a < -0.5f && b > -0.5f)   lo = 0.0f;
    if (a < 511.5f && b > 511.5f) hi = 511.0f;
}

// ONE setup kernel: per-batch params + per-tile staging window.
__global__ void setup_kernel(
    const float* __restrict__ u_angle, const float* __restrict__ u_scale,
    const float* __restrict__ u_trans, const float* __restrict__ u_bright,
    const float* __restrict__ u_contrast, const float* __restrict__ u_sat,
    const int* __restrict__ m_flip, const int* __restrict__ m_rot,
    const int* __restrict__ m_scale, const int* __restrict__ m_trans,
    const int* __restrict__ m_bright, const int* __restrict__ m_contrast,
    const int* __restrict__ m_sat, const int* __restrict__ m_cut,
    const int* __restrict__ y0, const int* __restrict__ x0)
{
    const int gid = blockIdx.x * 256 + threadIdx.x;
    const int b = gid >> 9;
    const int t = gid & (NTILES - 1);

    const float PI = 3.14159265358979323846f;
    const float angle = (m_rot[b] > 0) ? (u_angle[b] * 2.0f - 1.0f) * PI : 0.0f;
    const float sc    = (m_scale[b] > 0) ? (u_scale[b] * 2.0f - 1.0f) * 0.2f + 1.0f : 1.0f;
    const float tr    = (m_trans[b] > 0) ? (u_trans[b] * 2.0f - 1.0f) * 0.125f : 0.0f;
    const float ca = cosf(angle);
    const float sa = sinf(angle);
    const float m00 = sc * ca, m01 = -sc * sa;
    const float m10 = sc * sa, m11 =  sc * ca;

    const float S = 512.0f / 511.0f;
    float Ax = m00 * S, Bx = m01 * S;
    float Cx = (tr - m00 - m01) * 256.0f + 255.5f;
    float Ay = m10 * S, By = m11 * S;
    float Cy = (tr - m10 - m11) * 256.0f + 255.5f;
    if (m_flip[b] > 0) {            // flip folded via mirror (commutes)
        Ax = -Ax; Bx = -Bx; Cx = 511.0f - Cx;
    }

    if (t == 0) {
        BatchParams p;
        p.Ax = Ax; p.Bx = Bx; p.Cx = Cx;
        p.Ay = Ay; p.By = By; p.Cy = Cy;
        p.bb = (m_bright[b]   > 0) ? u_bright[b] * 0.2f   : 0.0f;
        p.cc = (m_contrast[b] > 0) ? u_contrast[b] + 0.5f : 1.0f;
        p.ss = (m_sat[b]      > 0) ? u_sat[b] * 2.0f      : 1.0f;
        p.cut = m_cut[b];
        p.y0 = y0[b];
        p.x0 = x0[b];
        p.vec = (m_rot[b] > 0) ? 1 : 0;
        p.pad0 = p.pad1 = p.pad2 = 0;
        g_params[b] = p;
    }

    const int tx0 = (t & 15) << 5;
    const int ty0 = (t >> 4) << 4;
    const float xA = (float)tx0, xB = (float)(tx0 + TW - 1);
    const float yA = (float)ty0, yB = (float)(ty0 + TH - 1);
    const float rxa = fminf(Ax * xA, Ax * xB) + fminf(Bx * yA, Bx * yB) + Cx - 0.01f;
    const float rxb = fmaxf(Ax * xA, Ax * xB) + fmaxf(Bx * yA, Bx * yB) + Cx + 0.01f;
    const float rya = fminf(Ay * xA, Ay * xB) + fminf(By * yA, By * yB) + Cy - 0.01f;
    const float ryb = fmaxf(Ay * xA, Ay * xB) + fmaxf(By * yA, By * yB) + Cy + 0.01f;

    const int interior = (rxa >= 0.0f && rxb < 511.0f &&
                          rya >= 0.0f && ryb < 511.0f) ? 1 : 0;

    float lox, hix, loy, hiy;
    reflect_range(rxa, rxb, lox, hix);
    reflect_range(rya, ryb, loy, hiy);

    const int xa    = ((int)floorf(lox)) & ~3;
    const int ys0   = (int)floorf(loy);
    const int rows  = min((int)floorf(hiy) + 2 - ys0, SBH);
    const int width = (int)floorf(hix) + 2 - xa;        // taps [xa .. xa+width-1]
    const int cols4 = min((width + 3) >> 2, SBW >> 2);

    g_tile[gid] = make_int4(xa, ys0, rows | (cols4 << 8) | (interior << 16), 0);
}

__device__ __forceinline__ float clip1(float v) {
    return fminf(fmaxf(v, -1.0f), 1.0f);
}

__device__ __forceinline__ void colorize(float r[3], const BatchParams& p) {
    r[0] = clip1(clip1(r[0] + p.bb) * p.cc);
    r[1] = clip1(clip1(r[1] + p.bb) * p.cc);
    r[2] = clip1(clip1(r[2] + p.bb) * p.cc);
    const float gray = (r[0] + r[1] + r[2]) * (1.0f / 3.0f);
    r[0] = clip1(gray + p.ss * (r[0] - gray));
    r[1] = clip1(gray + p.ss * (r[1] - gray));
    r[2] = clip1(gray + p.ss * (r[2] - gray));
}

// Sample from fp32 smem: adjacent taps merge into LDS.64.
__device__ __forceinline__ void sample_smem(
    const float* __restrict__ s, int base, float wx, float wy, float r[3]) {
    #pragma unroll
    for (int c = 0; c < Cn; c++) {
        const float* sp = s + c * SCH + base;
        const float v00 = sp[0];
        const float v01 = sp[1];
        const float v10 = sp[SBW];
        const float v11 = sp[SBW + 1];
        const float top = v00 + wx * (v01 - v00);
        const float bot = v10 + wx * (v11 - v10);
        r[c] = top + wy * (bot - top);
    }
}

__device__ __forceinline__ void gather_gmem(
    const float* __restrict__ img, unsigned img_base,
    float fx, float fy, bool interior, float r[3]) {
    if (!interior) {
        fx = reflect_coord(fx, (float)Wn);
        fy = reflect_coord(fy, (float)Hn);
    }
    const float x0f = floorf(fx);
    const float y0f = floorf(fy);
    const float wx = fx - x0f;
    const float wy = fy - y0f;
    const int xi0 = (int)x0f;
    const int yi0 = (int)y0f;
    const int xi1 = interior ? xi0 + 1 : min(xi0 + 1, Wn - 1);
    const int yi1 = interior ? yi0 + 1 : min(yi0 + 1, Hn - 1);
    const unsigned o00 = (unsigned)yi0 * Wn + xi0;
    const unsigned o01 = (unsigned)yi0 * Wn + xi1;
    const unsigned o10 = (unsigned)yi1 * Wn + xi0;
    const unsigned o11 = (unsigned)yi1 * Wn + xi1;
    #pragma unroll
    for (int c = 0; c < Cn; c++) {
        const float* ic = img + img_base + (unsigned)c * HW;
        const float v00 = __ldg(ic + o00);
        const float v01 = __ldg(ic + o01);
        const float v10 = __ldg(ic + o10);
        const float v11 = __ldg(ic + o11);
        const float top = v00 + wx * (v01 - v00);
        const float bot = v10 + wx * (v11 - v10);
        r[c] = top + wy * (bot - top);
    }
}

__global__ void __launch_bounds__(256) augment_kernel(
    const float* __restrict__ images,
    const float* __restrict__ noise,
    float* __restrict__ out)
{
    __shared__ __align__(16) float s_img[Cn * SCH];   // 29.3 KB

    const int b = blockIdx.y;
    const BatchParams p = g_params[b];

    const int t   = blockIdx.x;
    const int tx0 = (t & 15) << 5;
    const int ty0 = (t >> 4) << 4;

    const int tid = threadIdx.x;
    const int x = tx0 + ((tid & 15) << 1);   // 2 px/thread: x, x+1
    const int y = ty0 + (tid >> 4);

    const unsigned img_base = (unsigned)b * CHW;
    const unsigned oi = img_base + (unsigned)y * Wn + x;

    // ---- full-cut tile: float4 noise copy ----
    if (p.cut > 0 &&
        tx0 >= p.x0 && tx0 + TW <= p.x0 + CUT_W &&
        ty0 >= p.y0 && ty0 + TH <= p.y0 + CUT_H) {
        #pragma unroll
        for (int i = tid; i < 384; i += 256) {      // 3ch * 16 rows * 8 f4
            const int ch  = i >> 7;
            const int rem = i & 127;
            const unsigned a = img_base + (unsigned)ch * HW +
                               (unsigned)(ty0 + (rem >> 3)) * Wn + tx0 + ((rem & 7) << 2);
            *(float4*)(out + a) = *(const float4*)(noise + a);
        }
        return;
    }

    const int4 ti = __ldg(&g_tile[b * NTILES + t]);

    float fx0 = p.Ax * (float)x + p.Bx * (float)y + p.Cx;
    float fy0 = p.Ay * (float)x + p.By * (float)y + p.Cy;
    float fx1 = fx0 + p.Ax;
    float fy1 = fy0 + p.Ay;

    float r0[3], r1[3];

    if (p.vec) {
        // ================= staged path: ALL rotated tiles =================
        const int xa    = ti.x;
        const int ys0   = ti.y;
        const int rows  = ti.z & 0xff;
        const int cols4 = (ti.z >> 8) & 0xff;
        const bool interior = (ti.z >> 16) != 0;

        // Stage rows x cols4 float4 per channel. Exact float-reciprocal row
        // split (i < rows*cols4 <= 611, exact in fp32 with the +0.5 bias).
        const float invc = 1.0f / (float)cols4;
        const int total = rows * cols4;
        for (int i = tid; i < total; i += 256) {
            const int rr = (int)(((float)i + 0.5f) * invc);
            const int c4 = i - rr * cols4;
            const int gy = min(ys0 + rr, Hn - 1);
            const int gx = min(xa + (c4 << 2), Wn - 4);
            const unsigned ga = img_base + (unsigned)gy * Wn + gx;
            const int      sa = rr * SBW + (c4 << 2);
            *(float4*)&s_img[sa]           = *(const float4*)(images + ga);
            *(float4*)&s_img[SCH + sa]     = *(const float4*)(images + ga + HW);
            *(float4*)&s_img[2 * SCH + sa] = *(const float4*)(images + ga + 2 * HW);
        }
        __syncthreads();

        if (!interior) {            // block-uniform
            fx0 = reflect_coord(fx0, (float)Wn);
            fy0 = reflect_coord(fy0, (float)Hn);
            fx1 = reflect_coord(fx1, (float)Wn);
            fy1 = reflect_coord(fy1, (float)Hn);
        }
        {
            const float x0f = floorf(fx0), y0f = floorf(fy0);
            const int base = ((int)y0f - ys0) * SBW + ((int)x0f - xa);
            sample_smem(s_img, base, fx0 - x0f, fy0 - y0f, r0);
        }
        {
            const float x0f = floorf(fx1), y0f = floorf(fy1);
            const int base = ((int)y0f - ys0) * SBW + ((int)x0f - xa);
            sample_smem(s_img, base, fx1 - x0f, fy1 - y0f, r1);
        }
    } else {
        // ================= scalar path: unrotated batches =================
        const bool interior = (ti.z >> 16) != 0;
        gather_gmem(images, img_base, fx0, fy0, interior, r0);
        gather_gmem(images, img_base, fx1, fy1, interior, r1);
    }

    colorize(r0, p);
    colorize(r1, p);

    // ---- cutout overrides (per pixel) ----
    if (p.cut > 0 && y >= p.y0 && y < p.y0 + CUT_H) {
        if (x >= p.x0 && x < p.x0 + CUT_W) {
            r0[0] = noise[oi];
            r0[1] = noise[oi + HW];
            r0[2] = noise[oi + 2 * HW];
        }
        if (x + 1 >= p.x0 && x + 1 < p.x0 + CUT_W) {
            r1[0] = noise[oi + 1];
            r1[1] = noise[oi + 1 + HW];
            r1[2] = noise[oi + 1 + 2 * HW];
        }
    }

    *(float2*)(out + oi)          = make_float2(r0[0], r1[0]);
    *(float2*)(out + oi + HW)     = make_float2(r0[1], r1[1]);
    *(float2*)(out + oi + 2 * HW) = make_float2(r0[2], r1[2]);
}

extern "C" void kernel_launch(void* const* d_in, const int* in_sizes, int n_in,
                              void* d_out, int out_size) {
    const float* images     = (const float*)d_in[0];
    const float* u_angle    = (const float*)d_in[1];
    const float* u_scale    = (const float*)d_in[2];
    const float* u_trans    = (const float*)d_in[3];
    const float* u_bright   = (const float*)d_in[4];
    const float* u_contrast = (const float*)d_in[5];
    const float* u_sat      = (const float*)d_in[6];
    const float* noise      = (const float*)d_in[7];
    const int*   m_flip     = (const int*)d_in[8];
    const int*   m_rot      = (const int*)d_in[9];
    const int*   m_scale    = (const int*)d_in[10];
    const int*   m_trans    = (const int*)d_in[11];
    const int*   m_bright   = (const int*)d_in[12];
    const int*   m_contrast = (const int*)d_in[13];
    const int*   m_sat      = (const int*)d_in[14];
    const int*   m_cut      = (const int*)d_in[15];
    const int*   y0         = (const int*)d_in[16];
    const int*   x0         = (const int*)d_in[17];
    float* out = (float*)d_out;

    setup_kernel<<<(Bn * NTILES) / 256, 256>>>(
        u_angle, u_scale, u_trans, u_bright, u_contrast, u_sat,
        m_flip, m_rot, m_scale, m_trans, m_bright, m_contrast,
        m_sat, m_cut, y0, x0);

    dim3 block(256);
    dim3 grid(NTILES, Bn);
    augment_kernel<<<grid, block>>>(images, noise, out);
}

// round 15
// speedup vs baseline: 1.0367x; 1.0367x over previous
#include <cuda_runtime.h>
#include <math.h>

#define Bn 64
#define Cn 3
#define Hn 512
#define Wn 512
#define HW (Hn * Wn)
#define CHW (Cn * HW)
#define CUT_H 256
#define CUT_W 256

#define TW 32              // tile width (x)
#define TH 16              // tile height (y)
#define NTILES 512         // (512/32)*(512/16) tiles per batch
#define SBH 44             // staged rows (worst case 44: extent 41.42 + floor + taps)
#define SBW 48             // smem row stride (worst tap index 46, +1 neighbor = 47)
#define COLS4 12           // float4 per staged row (48 floats, covers width <= 47)
#define SCH (SBH * SBW)    // floats per channel (2112)

struct __align__(16) BatchParams {
    float Ax, Bx, Cx, Ay, By, Cy;   // fx = Ax*x + Bx*y + Cx (flip folded in)
    float bb, cc, ss;
    int   cut, y0, x0;
    int   vec, pad0, pad1, pad2;
};

__device__ BatchParams g_params[Bn];
__device__ int4 g_tile[Bn * NTILES];   // {xa, ys0, rows, interior}

__device__ __forceinline__ float reflect_coord(float v, float size) {
    v = fabsf(v + 0.5f);
    v = fmodf(v, 2.0f * size);
    v = fminf(v, 2.0f * size - v);
    return fminf(fmaxf(v - 0.5f, 0.0f), size - 1.0f);
}

__device__ __forceinline__ void reflect_range(float a, float b,
                                              float& lo, float& hi) {
    const float ra = reflect_coord(a, 512.0f);
    const float rb = reflect_coord(b, 512.0f);
    lo = fminf(ra, rb);
    hi = fmaxf(ra, rb);
    if (a < -0.5f && b > -0.5f)   lo = 0.0f;
    if (a < 511.5f && b > 511.5f) hi = 511.0f;
}

// ONE setup kernel: per-batch params + per-tile staging window.
__global__ void setup_kernel(
    const float* __restrict__ u_angle, const float* __restrict__ u_scale,
    const float* __restrict__ u_trans, const float* __restrict__ u_bright,
    const float* __restrict__ u_contrast, const float* __restrict__ u_sat,
    const int* __restrict__ m_flip, const int* __restrict__ m_rot,
    const int* __restrict__ m_scale, const int* __restrict__ m_trans,
    const int* __restrict__ m_bright, const int* __restrict__ m_contrast,
    const int* __restrict__ m_sat, const int* __restrict__ m_cut,
    const int* __restrict__ y0, const int* __restrict__ x0)
{
    const int gid = blockIdx.x * 256 + threadIdx.x;
    const int b = gid >> 9;
    const int t = gid & (NTILES - 1);

    const float PI = 3.14159265358979323846f;
    const float angle = (m_rot[b] > 0) ? (u_angle[b] * 2.0f - 1.0f) * PI : 0.0f;
    const float sc    = (m_scale[b] > 0) ? (u_scale[b] * 2.0f - 1.0f) * 0.2f + 1.0f : 1.0f;
    const float tr    = (m_trans[b] > 0) ? (u_trans[b] * 2.0f - 1.0f) * 0.125f : 0.0f;
    const float ca = cosf(angle);
    const float sa = sinf(angle);
    const float m00 = sc * ca, m01 = -sc * sa;
    const float m10 = sc * sa, m11 =  sc * ca;

    const float S = 512.0f / 511.0f;
    float Ax = m00 * S, Bx = m01 * S;
    float Cx = (tr - m00 - m01) * 256.0f + 255.5f;
    float Ay = m10 * S, By = m11 * S;
    float Cy = (tr - m10 - m11) * 256.0f + 255.5f;
    if (m_flip[b] > 0) {            // flip folded via mirror (commutes)
        Ax = -Ax; Bx = -Bx; Cx = 511.0f - Cx;
    }

    if (t == 0) {
        BatchParams p;
        p.Ax = Ax; p.Bx = Bx; p.Cx = Cx;
        p.Ay = Ay; p.By = By; p.Cy = Cy;
        p.bb = (m_bright[b]   > 0) ? u_bright[b] * 0.2f   : 0.0f;
        p.cc = (m_contrast[b] > 0) ? u_contrast[b] + 0.5f : 1.0f;
        p.ss = (m_sat[b]      > 0) ? u_sat[b] * 2.0f      : 1.0f;
        p.cut = m_cut[b];
        p.y0 = y0[b];
        p.x0 = x0[b];
        p.vec = (m_rot[b] > 0) ? 1 : 0;
        p.pad0 = p.pad1 = p.pad2 = 0;
        g_params[b] = p;
    }

    const int tx0 = (t & 15) << 5;
    const int ty0 = (t >> 4) << 4;
    const float xA = (float)tx0, xB = (float)(tx0 + TW - 1);
    const float yA = (float)ty0, yB = (float)(ty0 + TH - 1);
    const float rxa = fminf(Ax * xA, Ax * xB) + fminf(Bx * yA, Bx * yB) + Cx - 0.01f;
    const float rxb = fmaxf(Ax * xA, Ax * xB) + fmaxf(Bx * yA, Bx * yB) + Cx + 0.01f;
    const float rya = fminf(Ay * xA, Ay * xB) + fminf(By * yA, By * yB) + Cy - 0.01f;
    const float ryb = fmaxf(Ay * xA, Ay * xB) + fmaxf(By * yA, By * yB) + Cy + 0.01f;

    const int interior = (rxa >= 0.0f && rxb < 511.0f &&
                          rya >= 0.0f && ryb < 511.0f) ? 1 : 0;

    float lox, hix, loy, hiy;
    reflect_range(rxa, rxb, lox, hix);
    reflect_range(rya, ryb, loy, hiy);

    const int xa   = ((int)floorf(lox)) & ~3;
    const int ys0  = (int)floorf(loy);
    const int rows = min((int)floorf(hiy) + 2 - ys0, SBH);

    g_tile[gid] = make_int4(xa, ys0, rows, interior);
}

__device__ __forceinline__ float clip1(float v) {
    return fminf(fmaxf(v, -1.0f), 1.0f);
}

__device__ __forceinline__ void colorize(float r[3], const BatchParams& p) {
    r[0] = clip1(clip1(r[0] + p.bb) * p.cc);
    r[1] = clip1(clip1(r[1] + p.bb) * p.cc);
    r[2] = clip1(clip1(r[2] + p.bb) * p.cc);
    const float gray = (r[0] + r[1] + r[2]) * (1.0f / 3.0f);
    r[0] = clip1(gray + p.ss * (r[0] - gray));
    r[1] = clip1(gray + p.ss * (r[1] - gray));
    r[2] = clip1(gray + p.ss * (r[2] - gray));
}

// Sample from fp32 smem: adjacent taps merge into LDS.64.
__device__ __forceinline__ void sample_smem(
    const float* __restrict__ s, int base, float wx, float wy, float r[3]) {
    #pragma unroll
    for (int c = 0; c < Cn; c++) {
        const float* sp = s + c * SCH + base;
        const float v00 = sp[0];
        const float v01 = sp[1];
        const float v10 = sp[SBW];
        const float v11 = sp[SBW + 1];
        const float top = v00 + wx * (v01 - v00);
        const float bot = v10 + wx * (v11 - v10);
        r[c] = top + wy * (bot - top);
    }
}

__device__ __forceinline__ void gather_gmem(
    const float* __restrict__ img, unsigned img_base,
    float fx, float fy, bool interior, float r[3]) {
    if (!interior) {
        fx = reflect_coord(fx, (float)Wn);
        fy = reflect_coord(fy, (float)Hn);
    }
    const float x0f = floorf(fx);
    const float y0f = floorf(fy);
    const float wx = fx - x0f;
    const float wy = fy - y0f;
    const int xi0 = (int)x0f;
    const int yi0 = (int)y0f;
    const int xi1 = interior ? xi0 + 1 : min(xi0 + 1, Wn - 1);
    const int yi1 = interior ? yi0 + 1 : min(yi0 + 1, Hn - 1);
    const unsigned o00 = (unsigned)yi0 * Wn + xi0;
    const unsigned o01 = (unsigned)yi0 * Wn + xi1;
    const unsigned o10 = (unsigned)yi1 * Wn + xi0;
    const unsigned o11 = (unsigned)yi1 * Wn + xi1;
    #pragma unroll
    for (int c = 0; c < Cn; c++) {
        const float* ic = img + img_base + (unsigned)c * HW;
        const float v00 = __ldg(ic + o00);
        const float v01 = __ldg(ic + o01);
        const float v10 = __ldg(ic + o10);
        const float v11 = __ldg(ic + o11);
        const float top = v00 + wx * (v01 - v00);
        const float bot = v10 + wx * (v11 - v10);
        r[c] = top + wy * (bot - top);
    }
}

__global__ void __launch_bounds__(256) augment_kernel(
    const float* __restrict__ images,
    const float* __restrict__ noise,
    float* __restrict__ out)
{
    __shared__ __align__(16) float s_img[Cn * SCH];   // 25.3 KB

    const int b = blockIdx.y;
    const BatchParams p = g_params[b];

    const int t   = blockIdx.x;
    const int tx0 = (t & 15) << 5;
    const int ty0 = (t >> 4) << 4;

    const int tid = threadIdx.x;
    const int x = tx0 + ((tid & 15) << 1);   // 2 px/thread: x, x+1
    const int y = ty0 + (tid >> 4);

    const unsigned img_base = (unsigned)b * CHW;
    const unsigned oi = img_base + (unsigned)y * Wn + x;

    // ---- full-cut tile: float4 noise copy ----
    if (p.cut > 0 &&
        tx0 >= p.x0 && tx0 + TW <= p.x0 + CUT_W &&
        ty0 >= p.y0 && ty0 + TH <= p.y0 + CUT_H) {
        #pragma unroll
        for (int i = tid; i < 384; i += 256) {      // 3ch * 16 rows * 8 f4
            const int ch  = i >> 7;
            const int rem = i & 127;
            const unsigned a = img_base + (unsigned)ch * HW +
                               (unsigned)(ty0 + (rem >> 3)) * Wn + tx0 + ((rem & 7) << 2);
            *(float4*)(out + a) = *(const float4*)(noise + a);
        }
        return;
    }

    const int4 ti = __ldg(&g_tile[b * NTILES + t]);

    float fx0 = p.Ax * (float)x + p.Bx * (float)y + p.Cx;
    float fy0 = p.Ay * (float)x + p.By * (float)y + p.Cy;
    float fx1 = fx0 + p.Ax;
    float fy1 = fy0 + p.Ay;

    float r0[3], r1[3];

    if (p.vec) {
        // ================= staged path: ALL rotated tiles =================
        const int xa   = ti.x;
        const int ys0  = ti.y;
        const int rows = ti.z;
        const bool interior = ti.w != 0;

        // Stage rows x COLS4 float4 per channel (constant cols -> div by 12
        // compiles to mul-shift).
        const int total = rows * COLS4;
        for (int i = tid; i < total; i += 256) {
            const int rr = i / COLS4;
            const int c4 = i - rr * COLS4;
            const int gy = min(ys0 + rr, Hn - 1);
            const int gx = min(xa + (c4 << 2), Wn - 4);
            const unsigned ga = img_base + (unsigned)gy * Wn + gx;
            const int      sa = rr * SBW + (c4 << 2);
            *(float4*)&s_img[sa]           = *(const float4*)(images + ga);
            *(float4*)&s_img[SCH + sa]     = *(const float4*)(images + ga + HW);
            *(float4*)&s_img[2 * SCH + sa] = *(const float4*)(images + ga + 2 * HW);
        }
        __syncthreads();

        if (!interior) {            // block-uniform
            fx0 = reflect_coord(fx0, (float)Wn);
            fy0 = reflect_coord(fy0, (float)Hn);
            fx1 = reflect_coord(fx1, (float)Wn);
            fy1 = reflect_coord(fy1, (float)Hn);
        }
        {
            const float x0f = floorf(fx0), y0f = floorf(fy0);
            const int base = ((int)y0f - ys0) * SBW + ((int)x0f - xa);
            sample_smem(s_img, base, fx0 - x0f, fy0 - y0f, r0);
        }
        {
            const float x0f = floorf(fx1), y0f = floorf(fy1);
            const int base = ((int)y0f - ys0) * SBW + ((int)x0f - xa);
            sample_smem(s_img, base, fx1 - x0f, fy1 - y0f, r1);
        }
    } else {
        // ================= scalar path: unrotated batches =================
        const bool interior = ti.w != 0;
        gather_gmem(images, img_base, fx0, fy0, interior, r0);
        gather_gmem(images, img_base, fx1, fy1, interior, r1);
    }

    colorize(r0, p);
    colorize(r1, p);

    // ---- cutout overrides (per pixel) ----
    if (p.cut > 0 && y >= p.y0 && y < p.y0 + CUT_H) {
        if (x >= p.x0 && x < p.x0 + CUT_W) {
            r0[0] = noise[oi];
            r0[1] = noise[oi + HW];
            r0[2] = noise[oi + 2 * HW];
        }
        if (x + 1 >= p.x0 && x + 1 < p.x0 + CUT_W) {
            r1[0] = noise[oi + 1];
            r1[1] = noise[oi + 1 + HW];
            r1[2] = noise[oi + 1 + 2 * HW];
        }
    }

    *(float2*)(out + oi)          = make_float2(r0[0], r1[0]);
    *(float2*)(out + oi + HW)     = make_float2(r0[1], r1[1]);
    *(float2*)(out + oi + 2 * HW) = make_float2(r0[2], r1[2]);
}

extern "C" void kernel_launch(void* const* d_in, const int* in_sizes, int n_in,
                              void* d_out, int out_size) {
    const float* images     = (const float*)d_in[0];
    const float* u_angle    = (const float*)d_in[1];
    const float* u_scale    = (const float*)d_in[2];
    const float* u_trans    = (const float*)d_in[3];
    const float* u_bright   = (const float*)d_in[4];
    const float* u_contrast = (const float*)d_in[5];
    const float* u_sat      = (const float*)d_in[6];
    const float* noise      = (const float*)d_in[7];
    const int*   m_flip     = (const int*)d_in[8];
    const int*   m_rot      = (const int*)d_in[9];
    const int*   m_scale    = (const int*)d_in[10];
    const int*   m_trans    = (const int*)d_in[11];
    const int*   m_bright   = (const int*)d_in[12];
    const int*   m_contrast = (const int*)d_in[13];
    const int*   m_sat      = (const int*)d_in[14];
    const int*   m_cut      = (const int*)d_in[15];
    const int*   y0         = (const int*)d_in[16];
    const int*   x0         = (const int*)d_in[17];
    float* out = (float*)d_out;

    setup_kernel<<<(Bn * NTILES) / 256, 256>>>(
        u_angle, u_scale, u_trans, u_bright, u_contrast, u_sat,
        m_flip, m_rot, m_scale, m_trans, m_bright, m_contrast,
        m_sat, m_cut, y0, x0);

    dim3 block(256);
    dim3 grid(NTILES, Bn);
    augment_kernel<<<grid, block>>>(images, noise, out);
}

// round 16
// speedup vs baseline: 1.0633x; 1.0257x over previous
#include <cuda_runtime.h>
#include <math.h>

#define Bn 64
#define Cn 3
#define Hn 512
#define Wn 512
#define HW (Hn * Wn)
#define CHW (Cn * HW)
#define CUT_H 256
#define CUT_W 256

#define TW 32              // tile width (x)
#define TH 16              // tile height (y)
#define NTILES 512         // (512/32)*(512/16) tiles per batch
#define SBH 44             // staged rows (worst case 44)
#define SBW 48             // smem row stride (worst tap index 46, +1 = 47)
#define COLS4 12           // float4 per staged row
#define SCH (SBH * SBW)    // floats per channel (2112)

struct __align__(16) BatchParams {
    float Ax, Bx, Cx, Ay, By, Cy;   // fx = Ax*x + Bx*y + Cx (flip folded in)
    float bb, cc, ss;
    int   cut, y0, x0;
    int   vec, pad0, pad1, pad2;
};

__device__ BatchParams g_params[Bn];
__device__ int4 g_tile[Bn * NTILES];   // {xa, ys0, rows, interior}

__device__ __forceinline__ float reflect_coord(float v, float size) {
    v = fabsf(v + 0.5f);
    v = fmodf(v, 2.0f * size);
    v = fminf(v, 2.0f * size - v);
    return fminf(fmaxf(v - 0.5f, 0.0f), size - 1.0f);
}

__device__ __forceinline__ void reflect_range(float a, float b,
                                              float& lo, float& hi) {
    const float ra = reflect_coord(a, 512.0f);
    const float rb = reflect_coord(b, 512.0f);
    lo = fminf(ra, rb);
    hi = fmaxf(ra, rb);
    if (a < -0.5f && b > -0.5f)   lo = 0.0f;
    if (a < 511.5f && b > 511.5f) hi = 511.0f;
}

// ONE setup kernel: per-batch params + per-tile staging window.
__global__ void setup_kernel(
    const float* __restrict__ u_angle, const float* __restrict__ u_scale,
    const float* __restrict__ u_trans, const float* __restrict__ u_bright,
    const float* __restrict__ u_contrast, const float* __restrict__ u_sat,
    const int* __restrict__ m_flip, const int* __restrict__ m_rot,
    const int* __restrict__ m_scale, const int* __restrict__ m_trans,
    const int* __restrict__ m_bright, const int* __restrict__ m_contrast,
    const int* __restrict__ m_sat, const int* __restrict__ m_cut,
    const int* __restrict__ y0, const int* __restrict__ x0)
{
    const int gid = blockIdx.x * 256 + threadIdx.x;
    const int b = gid >> 9;
    const int t = gid & (NTILES - 1);

    const float PI = 3.14159265358979323846f;
    const float angle = (m_rot[b] > 0) ? (u_angle[b] * 2.0f - 1.0f) * PI : 0.0f;
    const float sc    = (m_scale[b] > 0) ? (u_scale[b] * 2.0f - 1.0f) * 0.2f + 1.0f : 1.0f;
    const float tr    = (m_trans[b] > 0) ? (u_trans[b] * 2.0f - 1.0f) * 0.125f : 0.0f;
    const float ca = cosf(angle);
    const float sa = sinf(angle);
    const float m00 = sc * ca, m01 = -sc * sa;
    const float m10 = sc * sa, m11 =  sc * ca;

    const float S = 512.0f / 511.0f;
    float Ax = m00 * S, Bx = m01 * S;
    float Cx = (tr - m00 - m01) * 256.0f + 255.5f;
    float Ay = m10 * S, By = m11 * S;
    float Cy = (tr - m10 - m11) * 256.0f + 255.5f;
    if (m_flip[b] > 0) {            // flip folded via mirror (commutes)
        Ax = -Ax; Bx = -Bx; Cx = 511.0f - Cx;
    }

    if (t == 0) {
        BatchParams p;
        p.Ax = Ax; p.Bx = Bx; p.Cx = Cx;
        p.Ay = Ay; p.By = By; p.Cy = Cy;
        p.bb = (m_bright[b]   > 0) ? u_bright[b] * 0.2f   : 0.0f;
        p.cc = (m_contrast[b] > 0) ? u_contrast[b] + 0.5f : 1.0f;
        p.ss = (m_sat[b]      > 0) ? u_sat[b] * 2.0f      : 1.0f;
        p.cut = m_cut[b];
        p.y0 = y0[b];
        p.x0 = x0[b];
        p.vec = (m_rot[b] > 0) ? 1 : 0;
        p.pad0 = p.pad1 = p.pad2 = 0;
        g_params[b] = p;
    }

    const int tx0 = (t & 15) << 5;
    const int ty0 = (t >> 4) << 4;
    const float xA = (float)tx0, xB = (float)(tx0 + TW - 1);
    const float yA = (float)ty0, yB = (float)(ty0 + TH - 1);
    const float rxa = fminf(Ax * xA, Ax * xB) + fminf(Bx * yA, Bx * yB) + Cx - 0.01f;
    const float rxb = fmaxf(Ax * xA, Ax * xB) + fmaxf(Bx * yA, Bx * yB) + Cx + 0.01f;
    const float rya = fminf(Ay * xA, Ay * xB) + fminf(By * yA, By * yB) + Cy - 0.01f;
    const float ryb = fmaxf(Ay * xA, Ay * xB) + fmaxf(By * yA, By * yB) + Cy + 0.01f;

    const int interior = (rxa >= 0.0f && rxb < 511.0f &&
                          rya >= 0.0f && ryb < 511.0f) ? 1 : 0;

    float lox, hix, loy, hiy;
    reflect_range(rxa, rxb, lox, hix);
    reflect_range(rya, ryb, loy, hiy);

    const int xa   = ((int)floorf(lox)) & ~3;
    const int ys0  = (int)floorf(loy);
    const int rows = min((int)floorf(hiy) + 2 - ys0, SBH);

    g_tile[gid] = make_int4(xa, ys0, rows, interior);
}

__device__ __forceinline__ float clip1(float v) {
    return fminf(fmaxf(v, -1.0f), 1.0f);
}

__device__ __forceinline__ void colorize(float r[3], const BatchParams& p) {
    r[0] = clip1(clip1(r[0] + p.bb) * p.cc);
    r[1] = clip1(clip1(r[1] + p.bb) * p.cc);
    r[2] = clip1(clip1(r[2] + p.bb) * p.cc);
    const float gray = (r[0] + r[1] + r[2]) * (1.0f / 3.0f);
    r[0] = clip1(gray + p.ss * (r[0] - gray));
    r[1] = clip1(gray + p.ss * (r[1] - gray));
    r[2] = clip1(gray + p.ss * (r[2] - gray));
}

// Sample from fp32 smem: adjacent taps merge into LDS.64.
__device__ __forceinline__ void sample_smem(
    const float* __restrict__ s, int base, float wx, float wy, float r[3]) {
    #pragma unroll
    for (int c = 0; c < Cn; c++) {
        const float* sp = s + c * SCH + base;
        const float v00 = sp[0];
        const float v01 = sp[1];
        const float v10 = sp[SBW];
        const float v11 = sp[SBW + 1];
        const float top = v00 + wx * (v01 - v00);
        const float bot = v10 + wx * (v11 - v10);
        r[c] = top + wy * (bot - top);
    }
}

__global__ void __launch_bounds__(256) augment_kernel(
    const float* __restrict__ images,
    const float* __restrict__ noise,
    float* __restrict__ out)
{
    __shared__ __align__(16) float s_img[Cn * SCH];   // 25.3 KB

    const int b = blockIdx.y;
    const BatchParams p = g_params[b];

    const int t   = blockIdx.x;
    const int tx0 = (t & 15) << 5;
    const int ty0 = (t >> 4) << 4;

    const int tid  = threadIdx.x;
    const int lane = tid & 31;
    const int warp = tid >> 5;

    const unsigned img_base = (unsigned)b * CHW;

    // ---- full-cut tile: float4 noise copy ----
    if (p.cut > 0 &&
        tx0 >= p.x0 && tx0 + TW <= p.x0 + CUT_W &&
        ty0 >= p.y0 && ty0 + TH <= p.y0 + CUT_H) {
        #pragma unroll
        for (int i = tid; i < 384; i += 256) {      // 3ch * 16 rows * 8 f4
            const int ch  = i >> 7;
            const int rem = i & 127;
            const unsigned a = img_base + (unsigned)ch * HW +
                               (unsigned)(ty0 + (rem >> 3)) * Wn + tx0 + ((rem & 7) << 2);
            *(float4*)(out + a) = *(const float4*)(noise + a);
        }
        return;
    }

    const int4 ti = __ldg(&g_tile[b * NTILES + t]);
    const bool interior = ti.w != 0;

    if (p.vec) {
        // ========= staged path: rotated tiles (horizontal px pairs) =========
        const int xa   = ti.x;
        const int ys0  = ti.y;
        const int rows = ti.z;

        const int x = tx0 + ((tid & 15) << 1);   // 2 px/thread: x, x+1
        const int y = ty0 + (tid >> 4);
        const unsigned oi = img_base + (unsigned)y * Wn + x;

        const int total = rows * COLS4;
        for (int i = tid; i < total; i += 256) {
            const int rr = i / COLS4;
            const int c4 = i - rr * COLS4;
            const int gy = min(ys0 + rr, Hn - 1);
            const int gx = min(xa + (c4 << 2), Wn - 4);
            const unsigned ga = img_base + (unsigned)gy * Wn + gx;
            const int      sa = rr * SBW + (c4 << 2);
            *(float4*)&s_img[sa]           = *(const float4*)(images + ga);
            *(float4*)&s_img[SCH + sa]     = *(const float4*)(images + ga + HW);
            *(float4*)&s_img[2 * SCH + sa] = *(const float4*)(images + ga + 2 * HW);
        }
        __syncthreads();

        float fx0 = p.Ax * (float)x + p.Bx * (float)y + p.Cx;
        float fy0 = p.Ay * (float)x + p.By * (float)y + p.Cy;
        float fx1 = fx0 + p.Ax;
        float fy1 = fy0 + p.Ay;
        if (!interior) {            // block-uniform
            fx0 = reflect_coord(fx0, (float)Wn);
            fy0 = reflect_coord(fy0, (float)Hn);
            fx1 = reflect_coord(fx1, (float)Wn);
            fy1 = reflect_coord(fy1, (float)Hn);
        }

        float r0[3], r1[3];
        {
            const float x0f = floorf(fx0), y0f = floorf(fy0);
            const int base = ((int)y0f - ys0) * SBW + ((int)x0f - xa);
            sample_smem(s_img, base, fx0 - x0f, fy0 - y0f, r0);
        }
        {
            const float x0f = floorf(fx1), y0f = floorf(fy1);
            const int base = ((int)y0f - ys0) * SBW + ((int)x0f - xa);
            sample_smem(s_img, base, fx1 - x0f, fy1 - y0f, r1);
        }

        colorize(r0, p);
        colorize(r1, p);

        if (p.cut > 0 && y >= p.y0 && y < p.y0 + CUT_H) {
            if (x >= p.x0 && x < p.x0 + CUT_W) {
                r0[0] = noise[oi];
                r0[1] = noise[oi + HW];
                r0[2] = noise[oi + 2 * HW];
            }
            if (x + 1 >= p.x0 && x + 1 < p.x0 + CUT_W) {
                r1[0] = noise[oi + 1];
                r1[1] = noise[oi + 1 + HW];
                r1[2] = noise[oi + 1 + 2 * HW];
            }
        }

        *(float2*)(out + oi)          = make_float2(r0[0], r1[0]);
        *(float2*)(out + oi + HW)     = make_float2(r0[1], r1[1]);
        *(float2*)(out + oi + 2 * HW) = make_float2(r0[2], r1[2]);
    } else {
        // ===== scalar path: unrotated (separable: Bx == 0, Ay == 0) =====
        // Vertical px pairs: thread = (x, yA), (x, yA+1); warp = 32
        // consecutive x in ONE row-pair -> fy warp-uniform, every tap LDG
        // touches exactly one source row (minimal lines/instr).
        const int x  = tx0 + lane;
        const int yA = ty0 + (warp << 1);
        const int yB = yA + 1;
        const unsigned oiA = img_base + (unsigned)yA * Wn + x;
        const unsigned oiB = oiA + Wn;

        float fx  = p.Ax * (float)x + p.Cx;     // Bx == 0 exactly
        float fyA = p.By * (float)yA + p.Cy;    // Ay == 0 exactly
        float fyB = fyA + p.By;
        if (!interior) {
            fx  = reflect_coord(fx,  (float)Wn);
            fyA = reflect_coord(fyA, (float)Hn);
            fyB = reflect_coord(fyB, (float)Hn);
        }

        const float x0f = floorf(fx);
        const float wx  = fx - x0f;
        const int xi0 = (int)x0f;
        const int xi1 = interior ? xi0 + 1 : min(xi0 + 1, Wn - 1);

        const float yA0f = floorf(fyA);
        const float wyA  = fyA - yA0f;
        const int yA0 = (int)yA0f;
        const int yA1 = interior ? yA0 + 1 : min(yA0 + 1, Hn - 1);

        const float yB0f = floorf(fyB);
        const float wyB  = fyB - yB0f;
        const int yB0 = (int)yB0f;
        const int yB1 = interior ? yB0 + 1 : min(yB0 + 1, Hn - 1);

        const unsigned rA0 = (unsigned)yA0 * Wn;
        const unsigned rA1 = (unsigned)yA1 * Wn;
        const unsigned rB0 = (unsigned)yB0 * Wn;
        const unsigned rB1 = (unsigned)yB1 * Wn;

        float rA[3], rB[3];
        #pragma unroll
        for (int c = 0; c < Cn; c++) {
            const float* ic = images + img_base + (unsigned)c * HW;
            const float a00 = __ldg(ic + rA0 + xi0);
            const float a01 = __ldg(ic + rA0 + xi1);
            const float a10 = __ldg(ic + rA1 + xi0);
            const float a11 = __ldg(ic + rA1 + xi1);
            const float b00 = __ldg(ic + rB0 + xi0);
            const float b01 = __ldg(ic + rB0 + xi1);
            const float b10 = __ldg(ic + rB1 + xi0);
            const float b11 = __ldg(ic + rB1 + xi1);
            const float tA = a00 + wx * (a01 - a00);
            const float bA = a10 + wx * (a11 - a10);
            rA[c] = tA + wyA * (bA - tA);
            const float tB = b00 + wx * (b01 - b00);
            const float bB = b10 + wx * (b11 - b10);
            rB[c] = tB + wyB * (bB - tB);
        }

        colorize(rA, p);
        colorize(rB, p);

        if (p.cut > 0 && x >= p.x0 && x < p.x0 + CUT_W) {
            if (yA >= p.y0 && yA < p.y0 + CUT_H) {
                rA[0] = noise[oiA];
                rA[1] = noise[oiA + HW];
                rA[2] = noise[oiA + 2 * HW];
            }
            if (yB >= p.y0 && yB < p.y0 + CUT_H) {
                rB[0] = noise[oiB];
                rB[1] = noise[oiB + HW];
                rB[2] = noise[oiB + 2 * HW];
            }
        }

        out[oiA]          = rA[0];
        out[oiA + HW]     = rA[1];
        out[oiA + 2 * HW] = rA[2];
        out[oiB]          = rB[0];
        out[oiB + HW]     = rB[1];
        out[oiB + 2 * HW] = rB[2];
    }
}

extern "C" void kernel_launch(void* const* d_in, const int* in_sizes, int n_in,
                              void* d_out, int out_size) {
    const float* images     = (const float*)d_in[0];
    const float* u_angle    = (const float*)d_in[1];
    const float* u_scale    = (const float*)d_in[2];
    const float* u_trans    = (const float*)d_in[3];
    const float* u_bright   = (const float*)d_in[4];
    const float* u_contrast = (const float*)d_in[5];
    const float* u_sat      = (const float*)d_in[6];
    const float* noise      = (const float*)d_in[7];
    const int*   m_flip     = (const int*)d_in[8];
    const int*   m_rot      = (const int*)d_in[9];
    const int*   m_scale    = (const int*)d_in[10];
    const int*   m_trans    = (const int*)d_in[11];
    const int*   m_bright   = (const int*)d_in[12];
    const int*   m_contrast = (const int*)d_in[13];
    const int*   m_sat      = (const int*)d_in[14];
    const int*   m_cut      = (const int*)d_in[15];
    const int*   y0         = (const int*)d_in[16];
    const int*   x0         = (const int*)d_in[17];
    float* out = (float*)d_out;

    setup_kernel<<<(Bn * NTILES) / 256, 256>>>(
        u_angle, u_scale, u_trans, u_bright, u_contrast, u_sat,
        m_flip, m_rot, m_scale, m_trans, m_bright, m_contrast,
        m_sat, m_cut, y0, x0);

    dim3 block(256);
    dim3 grid(NTILES, Bn);
    augment_kernel<<<grid, block>>>(images, noise, out);
}

// round 17
// speedup vs baseline: 1.1239x; 1.0570x over previous
#include <cuda_runtime.h>
#include <math.h>

#define Bn 64
#define Cn 3
#define Hn 512
#define Wn 512
#define HW (Hn * Wn)
#define CHW (Cn * HW)
#define CUT_H 256
#define CUT_W 256

#define TW 32              // tile width (x)
#define TH 16              // tile height (y)
#define NTILES 512         // (512/32)*(512/16) tiles per batch
#define SBH 44             // staged rows capacity
#define SBW 44             // smem row stride (gcd(44,32)=4 -> conflict-light)
#define COLS4 11           // float4 per staged row (44 floats)
#define SCH (SBH * SBW)    // floats per channel (1936)

struct __align__(16) BatchParams {
    float Ax, Bx, Cx, Ay, By, Cy;   // fx = Ax*x + Bx*y + Cx (flip folded in)
    float bb, cc, ss;
    int   cut, y0, x0;
    int   vec, pad0, pad1, pad2;
};

__device__ BatchParams g_params[Bn];
__device__ int4 g_tile[Bn * NTILES];   // {xa, ys0, rows, interior|staged<<1}

__device__ __forceinline__ float reflect_coord(float v, float size) {
    v = fabsf(v + 0.5f);
    v = fmodf(v, 2.0f * size);
    v = fminf(v, 2.0f * size - v);
    return fminf(fmaxf(v - 0.5f, 0.0f), size - 1.0f);
}

__device__ __forceinline__ void reflect_range(float a, float b,
                                              float& lo, float& hi) {
    const float ra = reflect_coord(a, 512.0f);
    const float rb = reflect_coord(b, 512.0f);
    lo = fminf(ra, rb);
    hi = fmaxf(ra, rb);
    if (a < -0.5f && b > -0.5f)   lo = 0.0f;
    if (a < 511.5f && b > 511.5f) hi = 511.0f;
}

// ONE setup kernel: per-batch params + per-tile staging window.
__global__ void setup_kernel(
    const float* __restrict__ u_angle, const float* __restrict__ u_scale,
    const float* __restrict__ u_trans, const float* __restrict__ u_bright,
    const float* __restrict__ u_contrast, const float* __restrict__ u_sat,
    const int* __restrict__ m_flip, const int* __restrict__ m_rot,
    const int* __restrict__ m_scale, const int* __restrict__ m_trans,
    const int* __restrict__ m_bright, const int* __restrict__ m_contrast,
    const int* __restrict__ m_sat, const int* __restrict__ m_cut,
    const int* __restrict__ y0, const int* __restrict__ x0)
{
    const int gid = blockIdx.x * 256 + threadIdx.x;
    const int b = gid >> 9;
    const int t = gid & (NTILES - 1);

    const float PI = 3.14159265358979323846f;
    const float angle = (m_rot[b] > 0) ? (u_angle[b] * 2.0f - 1.0f) * PI : 0.0f;
    const float sc    = (m_scale[b] > 0) ? (u_scale[b] * 2.0f - 1.0f) * 0.2f + 1.0f : 1.0f;
    const float tr    = (m_trans[b] > 0) ? (u_trans[b] * 2.0f - 1.0f) * 0.125f : 0.0f;
    const float ca = cosf(angle);
    const float sa = sinf(angle);
    const float m00 = sc * ca, m01 = -sc * sa;
    const float m10 = sc * sa, m11 =  sc * ca;

    const float S = 512.0f / 511.0f;
    float Ax = m00 * S, Bx = m01 * S;
    float Cx = (tr - m00 - m01) * 256.0f + 255.5f;
    float Ay = m10 * S, By = m11 * S;
    float Cy = (tr - m10 - m11) * 256.0f + 255.5f;
    if (m_flip[b] > 0) {            // flip folded via mirror (commutes)
        Ax = -Ax; Bx = -Bx; Cx = 511.0f - Cx;
    }

    if (t == 0) {
        BatchParams p;
        p.Ax = Ax; p.Bx = Bx; p.Cx = Cx;
        p.Ay = Ay; p.By = By; p.Cy = Cy;
        p.bb = (m_bright[b]   > 0) ? u_bright[b] * 0.2f   : 0.0f;
        p.cc = (m_contrast[b] > 0) ? u_contrast[b] + 0.5f : 1.0f;
        p.ss = (m_sat[b]      > 0) ? u_sat[b] * 2.0f      : 1.0f;
        p.cut = m_cut[b];
        p.y0 = y0[b];
        p.x0 = x0[b];
        p.vec = (m_rot[b] > 0) ? 1 : 0;
        p.pad0 = p.pad1 = p.pad2 = 0;
        g_params[b] = p;
    }

    const int tx0 = (t & 15) << 5;
    const int ty0 = (t >> 4) << 4;
    const float xA = (float)tx0, xB = (float)(tx0 + TW - 1);
    const float yA = (float)ty0, yB = (float)(ty0 + TH - 1);
    const float rxa = fminf(Ax * xA, Ax * xB) + fminf(Bx * yA, Bx * yB) + Cx - 0.01f;
    const float rxb = fmaxf(Ax * xA, Ax * xB) + fmaxf(Bx * yA, Bx * yB) + Cx + 0.01f;
    const float rya = fminf(Ay * xA, Ay * xB) + fminf(By * yA, By * yB) + Cy - 0.01f;
    const float ryb = fmaxf(Ay * xA, Ay * xB) + fmaxf(By * yA, By * yB) + Cy + 0.01f;

    const int interior = (rxa >= 0.0f && rxb < 511.0f &&
                          rya >= 0.0f && ryb < 511.0f) ? 1 : 0;

    float lox, hix, loy, hiy;
    reflect_range(rxa, rxb, lox, hix);
    reflect_range(rya, ryb, loy, hiy);

    const int xa    = ((int)floorf(lox)) & ~3;
    const int ys0   = (int)floorf(loy);
    const int rows  = (int)floorf(hiy) + 2 - ys0;        // UNCLAMPED
    const int width = (int)floorf(hix) + 2 - xa;         // taps [xa..xa+width-1]

    // Stage only if the window provably fits the buffer; rare oversize
    // tiles (near-diagonal max-scale) fall back to the reflect-safe
    // scalar gather, which is correct for any tile.
    const int rot    = (m_rot[b] > 0) ? 1 : 0;
    const int staged = (rot && rows <= SBH && width <= SBW) ? 1 : 0;

    g_tile[gid] = make_int4(xa, ys0, rows, interior | (staged << 1));
}

__device__ __forceinline__ float clip1(float v) {
    return fminf(fmaxf(v, -1.0f), 1.0f);
}

__device__ __forceinline__ void colorize(float r[3], const BatchParams& p) {
    r[0] = clip1(clip1(r[0] + p.bb) * p.cc);
    r[1] = clip1(clip1(r[1] + p.bb) * p.cc);
    r[2] = clip1(clip1(r[2] + p.bb) * p.cc);
    const float gray = (r[0] + r[1] + r[2]) * (1.0f / 3.0f);
    r[0] = clip1(gray + p.ss * (r[0] - gray));
    r[1] = clip1(gray + p.ss * (r[1] - gray));
    r[2] = clip1(gray + p.ss * (r[2] - gray));
}

// Sample from fp32 smem: adjacent taps merge into LDS.64.
__device__ __forceinline__ void sample_smem(
    const float* __restrict__ s, int base, float wx, float wy, float r[3]) {
    #pragma unroll
    for (int c = 0; c < Cn; c++) {
        const float* sp = s + c * SCH + base;
        const float v00 = sp[0];
        const float v01 = sp[1];
        const float v10 = sp[SBW];
        const float v11 = sp[SBW + 1];
        const float top = v00 + wx * (v01 - v00);
        const float bot = v10 + wx * (v11 - v10);
        r[c] = top + wy * (bot - top);
    }
}

// Generic reflect-safe gather (works for ANY tile).
__device__ __forceinline__ void gather_gmem(
    const float* __restrict__ img, unsigned img_base,
    float fx, float fy, bool interior, float r[3]) {
    if (!interior) {
        fx = reflect_coord(fx, (float)Wn);
        fy = reflect_coord(fy, (float)Hn);
    }
    const float x0f = floorf(fx);
    const float y0f = floorf(fy);
    const float wx = fx - x0f;
    const float wy = fy - y0f;
    const int xi0 = (int)x0f;
    const int yi0 = (int)y0f;
    const int xi1 = interior ? xi0 + 1 : min(xi0 + 1, Wn - 1);
    const int yi1 = interior ? yi0 + 1 : min(yi0 + 1, Hn - 1);
    const unsigned o00 = (unsigned)yi0 * Wn + xi0;
    const unsigned o01 = (unsigned)yi0 * Wn + xi1;
    const unsigned o10 = (unsigned)yi1 * Wn + xi0;
    const unsigned o11 = (unsigned)yi1 * Wn + xi1;
    #pragma unroll
    for (int c = 0; c < Cn; c++) {
        const float* ic = img + img_base + (unsigned)c * HW;
        const float v00 = __ldg(ic + o00);
        const float v01 = __ldg(ic + o01);
        const float v10 = __ldg(ic + o10);
        const float v11 = __ldg(ic + o11);
        const float top = v00 + wx * (v01 - v00);
        const float bot = v10 + wx * (v11 - v10);
        r[c] = top + wy * (bot - top);
    }
}

__global__ void __launch_bounds__(256) augment_kernel(
    const float* __restrict__ images,
    const float* __restrict__ noise,
    float* __restrict__ out)
{
    __shared__ __align__(16) float s_img[Cn * SCH];   // 23.2 KB

    const int b = blockIdx.y;
    const BatchParams p = g_params[b];

    const int t   = blockIdx.x;
    const int tx0 = (t & 15) << 5;
    const int ty0 = (t >> 4) << 4;

    const int tid  = threadIdx.x;
    const int lane = tid & 31;
    const int warp = tid >> 5;

    const unsigned img_base = (unsigned)b * CHW;

    // ---- full-cut tile: float4 noise copy ----
    if (p.cut > 0 &&
        tx0 >= p.x0 && tx0 + TW <= p.x0 + CUT_W &&
        ty0 >= p.y0 && ty0 + TH <= p.y0 + CUT_H) {
        #pragma unroll
        for (int i = tid; i < 384; i += 256) {      // 3ch * 16 rows * 8 f4
            const int ch  = i >> 7;
            const int rem = i & 127;
            const unsigned a = img_base + (unsigned)ch * HW +
                               (unsigned)(ty0 + (rem >> 3)) * Wn + tx0 + ((rem & 7) << 2);
            *(float4*)(out + a) = *(const float4*)(noise + a);
        }
        return;
    }

    const int4 ti = __ldg(&g_tile[b * NTILES + t]);
    const bool interior = (ti.w & 1) != 0;
    const bool staged   = (ti.w & 2) != 0;

    if (staged) {
        // ====== staged path: rotated tiles that fit (horizontal pairs) ======
        const int xa   = ti.x;
        const int ys0  = ti.y;
        const int rows = ti.z;

        const int x = tx0 + ((tid & 15) << 1);   // 2 px/thread: x, x+1
        const int y = ty0 + (tid >> 4);
        const unsigned oi = img_base + (unsigned)y * Wn + x;

        const int total = rows * COLS4;
        for (int i = tid; i < total; i += 256) {
            const int rr = i / COLS4;
            const int c4 = i - rr * COLS4;
            const int gy = min(ys0 + rr, Hn - 1);
            const int gx = min(xa + (c4 << 2), Wn - 4);
            const unsigned ga = img_base + (unsigned)gy * Wn + gx;
            const int      sa = rr * SBW + (c4 << 2);
            *(float4*)&s_img[sa]           = *(const float4*)(images + ga);
            *(float4*)&s_img[SCH + sa]     = *(const float4*)(images + ga + HW);
            *(float4*)&s_img[2 * SCH + sa] = *(const float4*)(images + ga + 2 * HW);
        }
        __syncthreads();

        float fx0 = p.Ax * (float)x + p.Bx * (float)y + p.Cx;
        float fy0 = p.Ay * (float)x + p.By * (float)y + p.Cy;
        float fx1 = fx0 + p.Ax;
        float fy1 = fy0 + p.Ay;
        if (!interior) {            // block-uniform
            fx0 = reflect_coord(fx0, (float)Wn);
            fy0 = reflect_coord(fy0, (float)Hn);
            fx1 = reflect_coord(fx1, (float)Wn);
            fy1 = reflect_coord(fy1, (float)Hn);
        }

        float r0[3], r1[3];
        {
            const float x0f = floorf(fx0), y0f = floorf(fy0);
            const int base = ((int)y0f - ys0) * SBW + ((int)x0f - xa);
            sample_smem(s_img, base, fx0 - x0f, fy0 - y0f, r0);
        }
        {
            const float x0f = floorf(fx1), y0f = floorf(fy1);
            const int base = ((int)y0f - ys0) * SBW + ((int)x0f - xa);
            sample_smem(s_img, base, fx1 - x0f, fy1 - y0f, r1);
        }

        colorize(r0, p);
        colorize(r1, p);

        if (p.cut > 0 && y >= p.y0 && y < p.y0 + CUT_H) {
            if (x >= p.x0 && x < p.x0 + CUT_W) {
                r0[0] = noise[oi];
                r0[1] = noise[oi + HW];
                r0[2] = noise[oi + 2 * HW];
            }
            if (x + 1 >= p.x0 && x + 1 < p.x0 + CUT_W) {
                r1[0] = noise[oi + 1];
                r1[1] = noise[oi + 1 + HW];
                r1[2] = noise[oi + 1 + 2 * HW];
            }
        }

        *(float2*)(out + oi)          = make_float2(r0[0], r1[0]);
        *(float2*)(out + oi + HW)     = make_float2(r0[1], r1[1]);
        *(float2*)(out + oi + 2 * HW) = make_float2(r0[2], r1[2]);
    } else if (p.vec) {
        // ==== rotated tiles that DON'T fit the buffer (rare): generic gather
        const int x = tx0 + ((tid & 15) << 1);
        const int y = ty0 + (tid >> 4);
        const unsigned oi = img_base + (unsigned)y * Wn + x;

        const float fx0 = p.Ax * (float)x + p.Bx * (float)y + p.Cx;
        const float fy0 = p.Ay * (float)x + p.By * (float)y + p.Cy;

        float r0[3], r1[3];
        gather_gmem(images, img_base, fx0, fy0, interior, r0);
        gather_gmem(images, img_base, fx0 + p.Ax, fy0 + p.Ay, interior, r1);

        colorize(r0, p);
        colorize(r1, p);

        if (p.cut > 0 && y >= p.y0 && y < p.y0 + CUT_H) {
            if (x >= p.x0 && x < p.x0 + CUT_W) {
                r0[0] = noise[oi];
                r0[1] = noise[oi + HW];
                r0[2] = noise[oi + 2 * HW];
            }
            if (x + 1 >= p.x0 && x + 1 < p.x0 + CUT_W) {
                r1[0] = noise[oi + 1];
                r1[1] = noise[oi + 1 + HW];
                r1[2] = noise[oi + 1 + 2 * HW];
            }
        }

        *(float2*)(out + oi)          = make_float2(r0[0], r1[0]);
        *(float2*)(out + oi + HW)     = make_float2(r0[1], r1[1]);
        *(float2*)(out + oi + 2 * HW) = make_float2(r0[2], r1[2]);
    } else {
        // ===== scalar path: unrotated (separable: Bx == 0, Ay == 0) =====
        // Vertical px pairs: warp = 32 consecutive x in ONE row-pair ->
        // fy warp-uniform, each tap LDG touches exactly one source row.
        const int x  = tx0 + lane;
        const int yA = ty0 + (warp << 1);
        const int yB = yA + 1;
        const unsigned oiA = img_base + (unsigned)yA * Wn + x;
        const unsigned oiB = oiA + Wn;

        float fx  = p.Ax * (float)x + p.Cx;     // Bx == 0 exactly
        float fyA = p.By * (float)yA + p.Cy;    // Ay == 0 exactly
        float fyB = fyA + p.By;
        if (!interior) {
            fx  = reflect_coord(fx,  (float)Wn);
            fyA = reflect_coord(fyA, (float)Hn);
            fyB = reflect_coord(fyB, (float)Hn);
        }

        const float x0f = floorf(fx);
        const float wx  = fx - x0f;
        const int xi0 = (int)x0f;
        const int xi1 = interior ? xi0 + 1 : min(xi0 + 1, Wn - 1);

        const float yA0f = floorf(fyA);
        const float wyA  = fyA - yA0f;
        const int yA0 = (int)yA0f;
        const int yA1 = interior ? yA0 + 1 : min(yA0 + 1, Hn - 1);

        const float yB0f = floorf(fyB);
        const float wyB  = fyB - yB0f;
        const int yB0 = (int)yB0f;
        const int yB1 = interior ? yB0 + 1 : min(yB0 + 1, Hn - 1);

        const unsigned rA0 = (unsigned)yA0 * Wn;
        const unsigned rA1 = (unsigned)yA1 * Wn;
        const unsigned rB0 = (unsigned)yB0 * Wn;
        const unsigned rB1 = (unsigned)yB1 * Wn;

        float rA[3], rB[3];
        #pragma unroll
        for (int c = 0; c < Cn; c++) {
            const float* ic = images + img_base + (unsigned)c * HW;
            const float a00 = __ldg(ic + rA0 + xi0);
            const float a01 = __ldg(ic + rA0 + xi1);
            const float a10 = __ldg(ic + rA1 + xi0);
            const float a11 = __ldg(ic + rA1 + xi1);
            const float b00 = __ldg(ic + rB0 + xi0);
            const float b01 = __ldg(ic + rB0 + xi1);
            const float b10 = __ldg(ic + rB1 + xi0);
            const float b11 = __ldg(ic + rB1 + xi1);
            const float tA = a00 + wx * (a01 - a00);
            const float bA = a10 + wx * (a11 - a10);
            rA[c] = tA + wyA * (bA - tA);
            const float tB = b00 + wx * (b01 - b00);
            const float bB = b10 + wx * (b11 - b10);
            rB[c] = tB + wyB * (bB - tB);
        }

        colorize(rA, p);
        colorize(rB, p);

        if (p.cut > 0 && x >= p.x0 && x < p.x0 + CUT_W) {
            if (yA >= p.y0 && yA < p.y0 + CUT_H) {
                rA[0] = noise[oiA];
                rA[1] = noise[oiA + HW];
                rA[2] = noise[oiA + 2 * HW];
            }
            if (yB >= p.y0 && yB < p.y0 + CUT_H) {
                rB[0] = noise[oiB];
                rB[1] = noise[oiB + HW];
                rB[2] = noise[oiB + 2 * HW];
            }
        }

        out[oiA]          = rA[0];
        out[oiA + HW]     = rA[1];
        out[oiA + 2 * HW] = rA[2];
        out[oiB]          = rB[0];
        out[oiB + HW]     = rB[1];
        out[oiB + 2 * HW] = rB[2];
    }
}

extern "C" void kernel_launch(void* const* d_in, const int* in_sizes, int n_in,
                              void* d_out, int out_size) {
    const float* images     = (const float*)d_in[0];
    const float* u_angle    = (const float*)d_in[1];
    const float* u_scale    = (const float*)d_in[2];
    const float* u_trans    = (const float*)d_in[3];
    const float* u_bright   = (const float*)d_in[4];
    const float* u_contrast = (const float*)d_in[5];
    const float* u_sat      = (const float*)d_in[6];
    const float* noise      = (const float*)d_in[7];
    const int*   m_flip     = (const int*)d_in[8];
    const int*   m_rot      = (const int*)d_in[9];
    const int*   m_scale    = (const int*)d_in[10];
    const int*   m_trans    = (const int*)d_in[11];
    const int*   m_bright   = (const int*)d_in[12];
    const int*   m_contrast = (const int*)d_in[13];
    const int*   m_sat      = (const int*)d_in[14];
    const int*   m_cut      = (const int*)d_in[15];
    const int*   y0         = (const int*)d_in[16];
    const int*   x0         = (const int*)d_in[17];
    float* out = (float*)d_out;

    setup_kernel<<<(Bn * NTILES) / 256, 256>>>(
        u_angle, u_scale, u_trans, u_bright, u_contrast, u_sat,
        m_flip, m_rot, m_scale, m_trans, m_bright, m_contrast,
        m_sat, m_cut, y0, x0);

    dim3 block(256);
    dim3 grid(NTILES, Bn);
    augment_kernel<<<grid, block>>>(images, noise, out);
}